// round 1
// baseline (speedup 1.0000x reference)
#include <cuda_runtime.h>
#include <cstdint>

// Row-wise top-k threshold mask.
// x: [ROWS, COLS] fp32.  out[i,j] = x[i,j] if x[i,j] >= (k-th largest of row i) else 0.
// One CTA per row. Keys live in registers; 4-pass radix select (MSB-first, 8 bits).

constexpr int COLS       = 16384;
constexpr int THREADS    = 256;
constexpr int PER_THREAD = COLS / THREADS;   // 64
constexpr int VEC        = PER_THREAD / 4;   // 16 float4 per thread

// Order-preserving float -> uint32 key (larger float => larger key)
__device__ __forceinline__ unsigned f2key(float f) {
    unsigned u = __float_as_uint(f);
    return (u & 0x80000000u) ? ~u : (u | 0x80000000u);
}
__device__ __forceinline__ float key2f(unsigned k) {
    unsigned u = (k & 0x80000000u) ? (k & 0x7FFFFFFFu) : ~k;
    return __uint_as_float(u);
}

__global__ __launch_bounds__(THREADS, 2)
void topk_mask_kernel(const float* __restrict__ x,
                      float* __restrict__ out,
                      const int* __restrict__ kptr)
{
    __shared__ int      s_hist[256];
    __shared__ int      s_warp[8];     // per-warp partial sums for block scan
    __shared__ int      s_kk;
    __shared__ unsigned s_digit;

    const int      tid  = threadIdx.x;
    const int      lane = tid & 31;
    const size_t   base = (size_t)blockIdx.x * COLS;

    // ---- Load row into registers (coalesced float4), convert to keys ----
    unsigned keys[PER_THREAD];
    {
        const float4* xv = reinterpret_cast<const float4*>(x + base);
        #pragma unroll
        for (int j = 0; j < VEC; j++) {
            float4 v = xv[tid + j * THREADS];
            keys[4*j + 0] = f2key(v.x);
            keys[4*j + 1] = f2key(v.y);
            keys[4*j + 2] = f2key(v.z);
            keys[4*j + 3] = f2key(v.w);
        }
    }

    if (tid == 0) s_kk = (kptr != nullptr) ? kptr[0] : 64;

    unsigned prefix   = 0;
    unsigned prefmask = 0;

    // ---- 4-pass MSB-first radix select over register-resident keys ----
    for (int pass = 3; pass >= 0; pass--) {
        const int shift = pass * 8;

        s_hist[tid] = 0;
        __syncthreads();

        // Count (warp-aggregated smem atomics to avoid hot-bucket serialization)
        #pragma unroll
        for (int i = 0; i < PER_THREAD; i++) {
            const unsigned kv   = keys[i];
            const bool     cand = ((kv & prefmask) == prefix);
            const unsigned d    = cand ? ((kv >> shift) & 255u) : 0xFFFFFFFFu;
            const unsigned m    = __match_any_sync(0xFFFFFFFFu, d);
            if (cand && lane == (__ffs(m) - 1))
                atomicAdd(&s_hist[d], __popc(m));
        }
        __syncthreads();

        // Block suffix scan: thread t owns bucket b = 255 - t.
        // incl(t) = sum_{t'<=t} hist[255-t'] = count of keys with digit >= b
        const int h = s_hist[255 - tid];
        int v = h;
        #pragma unroll
        for (int o = 1; o < 32; o <<= 1) {
            int n = __shfl_up_sync(0xFFFFFFFFu, v, o);
            if (lane >= o) v += n;
        }
        if (lane == 31) s_warp[tid >> 5] = v;
        __syncthreads();
        if (tid < 8) {
            int ws = s_warp[tid];
            #pragma unroll
            for (int o = 1; o < 8; o <<= 1) {
                int n = __shfl_up_sync(0xFFu, ws, o);
                if (tid >= o) ws += n;
            }
            s_warp[tid] = ws;
        }
        const int kk_cur = s_kk;   // read BEFORE anyone updates it
        __syncthreads();
        const int incl   = v + ((tid >= 32) ? s_warp[(tid >> 5) - 1] : 0);
        const int cnt_gt = incl - h;

        // Exactly one bucket satisfies cnt_gt < kk <= cnt_ge
        if (cnt_gt < kk_cur && kk_cur <= incl) {
            s_digit = (unsigned)(255 - tid);
            s_kk    = kk_cur - cnt_gt;
        }
        __syncthreads();

        prefix   |= (s_digit << shift);
        prefmask |= (255u << shift);
        __syncthreads();   // protect s_digit/s_kk before next pass overwrites
    }

    const unsigned thresh = prefix;   // exact key of the k-th largest element

    // ---- Masked write-back from registers (coalesced float4) ----
    {
        float4* ov = reinterpret_cast<float4*>(out + base);
        #pragma unroll
        for (int j = 0; j < VEC; j++) {
            float4 r;
            r.x = (keys[4*j + 0] >= thresh) ? key2f(keys[4*j + 0]) : 0.0f;
            r.y = (keys[4*j + 1] >= thresh) ? key2f(keys[4*j + 1]) : 0.0f;
            r.z = (keys[4*j + 2] >= thresh) ? key2f(keys[4*j + 2]) : 0.0f;
            r.w = (keys[4*j + 3] >= thresh) ? key2f(keys[4*j + 3]) : 0.0f;
            ov[tid + j * THREADS] = r;
        }
    }
}

extern "C" void kernel_launch(void* const* d_in, const int* in_sizes, int n_in,
                              void* d_out, int out_size)
{
    const float* x  = (const float*)d_in[0];
    const int*   kp = (n_in >= 2) ? (const int*)d_in[1] : nullptr;
    float*       o  = (float*)d_out;

    const int rows = in_sizes[0] / COLS;
    topk_mask_kernel<<<rows, THREADS>>>(x, o, kp);
}

// round 2
// speedup vs baseline: 1.0000x; 1.0000x over previous
#include <cuda_runtime.h>
#include <cstdint>

// Row-wise top-k threshold mask.
// x: [ROWS, COLS] fp32.  out[i,j] = x[i,j] if x[i,j] >= (k-th largest of row i) else 0.
// One CTA per row. Keys live in registers; 4-pass radix select (MSB-first, 8 bits).

constexpr int COLS       = 16384;
constexpr int THREADS    = 256;
constexpr int PER_THREAD = COLS / THREADS;   // 64
constexpr int VEC        = PER_THREAD / 4;   // 16 float4 per thread

// Order-preserving float -> uint32 key (larger float => larger key)
__device__ __forceinline__ unsigned f2key(float f) {
    unsigned u = __float_as_uint(f);
    return (u & 0x80000000u) ? ~u : (u | 0x80000000u);
}
__device__ __forceinline__ float key2f(unsigned k) {
    unsigned u = (k & 0x80000000u) ? (k & 0x7FFFFFFFu) : ~k;
    return __uint_as_float(u);
}

__global__ __launch_bounds__(THREADS, 2)
void topk_mask_kernel(const float* __restrict__ x,
                      float* __restrict__ out,
                      const int* __restrict__ kptr)
{
    __shared__ int      s_hist[256];
    __shared__ int      s_warp[8];     // per-warp partial sums for block scan
    __shared__ int      s_kk;
    __shared__ unsigned s_digit;

    const int      tid  = threadIdx.x;
    const int      lane = tid & 31;
    const size_t   base = (size_t)blockIdx.x * COLS;

    // ---- Load row into registers (coalesced float4), convert to keys ----
    unsigned keys[PER_THREAD];
    {
        const float4* xv = reinterpret_cast<const float4*>(x + base);
        #pragma unroll
        for (int j = 0; j < VEC; j++) {
            float4 v = xv[tid + j * THREADS];
            keys[4*j + 0] = f2key(v.x);
            keys[4*j + 1] = f2key(v.y);
            keys[4*j + 2] = f2key(v.z);
            keys[4*j + 3] = f2key(v.w);
        }
    }

    if (tid == 0) s_kk = (kptr != nullptr) ? kptr[0] : 64;

    unsigned prefix   = 0;
    unsigned prefmask = 0;

    // ---- 4-pass MSB-first radix select over register-resident keys ----
    for (int pass = 3; pass >= 0; pass--) {
        const int shift = pass * 8;

        s_hist[tid] = 0;
        __syncthreads();

        // Count (warp-aggregated smem atomics to avoid hot-bucket serialization)
        #pragma unroll
        for (int i = 0; i < PER_THREAD; i++) {
            const unsigned kv   = keys[i];
            const bool     cand = ((kv & prefmask) == prefix);
            const unsigned d    = cand ? ((kv >> shift) & 255u) : 0xFFFFFFFFu;
            const unsigned m    = __match_any_sync(0xFFFFFFFFu, d);
            if (cand && lane == (__ffs(m) - 1))
                atomicAdd(&s_hist[d], __popc(m));
        }
        __syncthreads();

        // Block suffix scan: thread t owns bucket b = 255 - t.
        // incl(t) = sum_{t'<=t} hist[255-t'] = count of keys with digit >= b
        const int h = s_hist[255 - tid];
        int v = h;
        #pragma unroll
        for (int o = 1; o < 32; o <<= 1) {
            int n = __shfl_up_sync(0xFFFFFFFFu, v, o);
            if (lane >= o) v += n;
        }
        if (lane == 31) s_warp[tid >> 5] = v;
        __syncthreads();
        if (tid < 8) {
            int ws = s_warp[tid];
            #pragma unroll
            for (int o = 1; o < 8; o <<= 1) {
                int n = __shfl_up_sync(0xFFu, ws, o);
                if (tid >= o) ws += n;
            }
            s_warp[tid] = ws;
        }
        const int kk_cur = s_kk;   // read BEFORE anyone updates it
        __syncthreads();
        const int incl   = v + ((tid >= 32) ? s_warp[(tid >> 5) - 1] : 0);
        const int cnt_gt = incl - h;

        // Exactly one bucket satisfies cnt_gt < kk <= cnt_ge
        if (cnt_gt < kk_cur && kk_cur <= incl) {
            s_digit = (unsigned)(255 - tid);
            s_kk    = kk_cur - cnt_gt;
        }
        __syncthreads();

        prefix   |= (s_digit << shift);
        prefmask |= (255u << shift);
        __syncthreads();   // protect s_digit/s_kk before next pass overwrites
    }

    const unsigned thresh = prefix;   // exact key of the k-th largest element

    // ---- Masked write-back from registers (coalesced float4) ----
    {
        float4* ov = reinterpret_cast<float4*>(out + base);
        #pragma unroll
        for (int j = 0; j < VEC; j++) {
            float4 r;
            r.x = (keys[4*j + 0] >= thresh) ? key2f(keys[4*j + 0]) : 0.0f;
            r.y = (keys[4*j + 1] >= thresh) ? key2f(keys[4*j + 1]) : 0.0f;
            r.z = (keys[4*j + 2] >= thresh) ? key2f(keys[4*j + 2]) : 0.0f;
            r.w = (keys[4*j + 3] >= thresh) ? key2f(keys[4*j + 3]) : 0.0f;
            ov[tid + j * THREADS] = r;
        }
    }
}

extern "C" void kernel_launch(void* const* d_in, const int* in_sizes, int n_in,
                              void* d_out, int out_size)
{
    const float* x  = (const float*)d_in[0];
    const int*   kp = (n_in >= 2) ? (const int*)d_in[1] : nullptr;
    float*       o  = (float*)d_out;

    const int rows = in_sizes[0] / COLS;
    topk_mask_kernel<<<rows, THREADS>>>(x, o, kp);
}

// round 3
// speedup vs baseline: 1.7735x; 1.7734x over previous
#include <cuda_runtime.h>
#include <cstdint>

// Row-wise top-k threshold mask, radix-select with candidate compaction.
// x: [ROWS, 16384] fp32. out[i,j] = x[i,j] if x[i,j] >= (k-th largest of row i) else 0.
// One CTA per row; row keys staged in 64KB dynamic smem.

constexpr int COLS       = 16384;
constexpr int THREADS    = 512;
constexpr int PER_THREAD = COLS / THREADS;   // 32
constexpr int VEC        = PER_THREAD / 4;   // 8 x uint4 per thread
constexpr int CAP        = 1024;             // candidate buffer capacity

__device__ __forceinline__ unsigned f2key(float f) {
    unsigned u = __float_as_uint(f);
    return (u & 0x80000000u) ? ~u : (u | 0x80000000u);
}
__device__ __forceinline__ float key2f(unsigned k) {
    unsigned u = (k & 0x80000000u) ? (k & 0x7FFFFFFFu) : ~k;
    return __uint_as_float(u);
}

// Pick the bucket containing the kk-th largest; updates *s_kk in place.
// All THREADS threads must call. Returns chosen digit (broadcast).
__device__ __forceinline__ unsigned select_digit(
    int* s_hist, int* s_warp, int* s_kk, unsigned* s_digit, int tid, int lane)
{
    int h = 0, v = 0;
    if (tid < 256) {
        h = s_hist[255 - tid];
        v = h;
        #pragma unroll
        for (int o = 1; o < 32; o <<= 1) {
            int n = __shfl_up_sync(0xFFFFFFFFu, v, o);
            if (lane >= o) v += n;
        }
        if (lane == 31) s_warp[tid >> 5] = v;
    }
    __syncthreads();
    if (tid < 8) {
        int ws = s_warp[tid];
        #pragma unroll
        for (int o = 1; o < 8; o <<= 1) {
            int n = __shfl_up_sync(0xFFu, ws, o);
            if (tid >= o) ws += n;
        }
        s_warp[tid] = ws;
    }
    const int kk_cur = *s_kk;          // read before anyone updates it
    __syncthreads();
    if (tid < 256) {
        const int incl   = v + ((tid >= 32) ? s_warp[(tid >> 5) - 1] : 0); // count >= bucket
        const int cnt_gt = incl - h;                                       // count >  bucket
        if (cnt_gt < kk_cur && kk_cur <= incl) {
            *s_digit = (unsigned)(255 - tid);
            *s_kk    = kk_cur - cnt_gt;
        }
    }
    __syncthreads();
    return *s_digit;
}

__global__ __launch_bounds__(THREADS, 3)
void topk_mask_kernel(const float* __restrict__ x,
                      float* __restrict__ out,
                      const int* __restrict__ kptr)
{
    __shared__ int      s_hist[256];
    __shared__ int      s_warp[8];
    __shared__ unsigned s_cand[CAP];
    __shared__ int      s_ncand;
    __shared__ int      s_kk;
    __shared__ unsigned s_digit;
    extern __shared__ unsigned s_keys[];          // 16384 keys = 64KB

    const int    tid  = threadIdx.x;
    const int    lane = tid & 31;
    const size_t base = (size_t)blockIdx.x * COLS;

    if (tid < 256) s_hist[tid] = 0;
    if (tid == 0) { s_ncand = 0; s_kk = (kptr != nullptr) ? kptr[0] : 64; }
    __syncthreads();

    // ---- Load row (float4), convert, stage keys to smem, fused pass-1 hist ----
    {
        const float4* xv = reinterpret_cast<const float4*>(x + base);
        uint4*        kv = reinterpret_cast<uint4*>(s_keys);
        #pragma unroll
        for (int j = 0; j < VEC; j++) {
            float4 v = xv[tid + j * THREADS];
            uint4 kq;
            kq.x = f2key(v.x); kq.y = f2key(v.y);
            kq.z = f2key(v.z); kq.w = f2key(v.w);
            kv[tid + j * THREADS] = kq;
            unsigned ks[4] = {kq.x, kq.y, kq.z, kq.w};
            #pragma unroll
            for (int t = 0; t < 4; t++) {
                const unsigned d = ks[t] >> 24;
                const unsigned m = __match_any_sync(0xFFFFFFFFu, d);
                if (lane == (__ffs(m) - 1)) atomicAdd(&s_hist[d], __popc(m));
            }
        }
    }
    __syncthreads();

    unsigned prefix = select_digit(s_hist, s_warp, &s_kk, &s_digit, tid, lane) << 24;

    // ---- Compact candidates (top byte matches) + fused pass-2 hist ----
    if (tid < 256) s_hist[tid] = 0;
    __syncthreads();
    {
        const uint4* kv = reinterpret_cast<const uint4*>(s_keys);
        const unsigned d1 = prefix >> 24;
        #pragma unroll
        for (int j = 0; j < VEC; j++) {
            uint4 kq = kv[tid + j * THREADS];
            unsigned ks[4] = {kq.x, kq.y, kq.z, kq.w};
            #pragma unroll
            for (int t = 0; t < 4; t++) {
                const bool     cand = ((ks[t] >> 24) == d1);
                const unsigned d    = cand ? ((ks[t] >> 16) & 255u) : 0xFFFFFFFFu;
                const unsigned m    = __match_any_sync(0xFFFFFFFFu, d);
                if (cand) {
                    const int idx = atomicAdd(&s_ncand, 1);
                    if (idx < CAP) s_cand[idx] = ks[t];
                    if (lane == (__ffs(m) - 1)) atomicAdd(&s_hist[d], __popc(m));
                }
            }
        }
    }
    __syncthreads();
    const int  ncand  = s_ncand;
    const bool useBuf = (ncand <= CAP);

    prefix |= select_digit(s_hist, s_warp, &s_kk, &s_digit, tid, lane) << 16;

    // ---- Pass 3 (byte 1) over candidates ----
    if (tid < 256) s_hist[tid] = 0;
    __syncthreads();
    if (useBuf) {
        const int nloop = (ncand + THREADS - 1) / THREADS * THREADS;
        for (int i = tid; i < nloop; i += THREADS) {
            const unsigned key  = (i < ncand) ? s_cand[i] : 0u;
            const bool     cand = (i < ncand) && ((key >> 16) == (prefix >> 16));
            const unsigned d    = cand ? ((key >> 8) & 255u) : 0xFFFFFFFFu;
            const unsigned m    = __match_any_sync(0xFFFFFFFFu, d);
            if (cand && lane == (__ffs(m) - 1)) atomicAdd(&s_hist[d], __popc(m));
        }
    } else {
        #pragma unroll
        for (int j = 0; j < PER_THREAD; j++) {
            const unsigned key  = s_keys[tid + j * THREADS];
            const bool     cand = ((key >> 16) == (prefix >> 16));
            const unsigned d    = cand ? ((key >> 8) & 255u) : 0xFFFFFFFFu;
            const unsigned m    = __match_any_sync(0xFFFFFFFFu, d);
            if (cand && lane == (__ffs(m) - 1)) atomicAdd(&s_hist[d], __popc(m));
        }
    }
    __syncthreads();

    prefix |= select_digit(s_hist, s_warp, &s_kk, &s_digit, tid, lane) << 8;

    // ---- Pass 4 (byte 0) over candidates ----
    if (tid < 256) s_hist[tid] = 0;
    __syncthreads();
    if (useBuf) {
        const int nloop = (ncand + THREADS - 1) / THREADS * THREADS;
        for (int i = tid; i < nloop; i += THREADS) {
            const unsigned key  = (i < ncand) ? s_cand[i] : 0u;
            const bool     cand = (i < ncand) && ((key >> 8) == (prefix >> 8));
            const unsigned d    = cand ? (key & 255u) : 0xFFFFFFFFu;
            const unsigned m    = __match_any_sync(0xFFFFFFFFu, d);
            if (cand && lane == (__ffs(m) - 1)) atomicAdd(&s_hist[d], __popc(m));
        }
    } else {
        #pragma unroll
        for (int j = 0; j < PER_THREAD; j++) {
            const unsigned key  = s_keys[tid + j * THREADS];
            const bool     cand = ((key >> 8) == (prefix >> 8));
            const unsigned d    = cand ? (key & 255u) : 0xFFFFFFFFu;
            const unsigned m    = __match_any_sync(0xFFFFFFFFu, d);
            if (cand && lane == (__ffs(m) - 1)) atomicAdd(&s_hist[d], __popc(m));
        }
    }
    __syncthreads();

    const unsigned thresh = prefix | select_digit(s_hist, s_warp, &s_kk, &s_digit, tid, lane);

    // ---- Masked write-back from smem keys (coalesced float4) ----
    {
        const uint4* kv = reinterpret_cast<const uint4*>(s_keys);
        float4*      ov = reinterpret_cast<float4*>(out + base);
        #pragma unroll
        for (int j = 0; j < VEC; j++) {
            uint4 kq = kv[tid + j * THREADS];
            float4 r;
            r.x = (kq.x >= thresh) ? key2f(kq.x) : 0.0f;
            r.y = (kq.y >= thresh) ? key2f(kq.y) : 0.0f;
            r.z = (kq.z >= thresh) ? key2f(kq.z) : 0.0f;
            r.w = (kq.w >= thresh) ? key2f(kq.w) : 0.0f;
            ov[tid + j * THREADS] = r;
        }
    }
}

extern "C" void kernel_launch(void* const* d_in, const int* in_sizes, int n_in,
                              void* d_out, int out_size)
{
    const float* x  = (const float*)d_in[0];
    const int*   kp = (n_in >= 2) ? (const int*)d_in[1] : nullptr;
    float*       o  = (float*)d_out;

    const int rows = in_sizes[0] / COLS;
    const int dyn  = COLS * (int)sizeof(unsigned);   // 64KB key stage

    cudaFuncSetAttribute(topk_mask_kernel,
                         cudaFuncAttributeMaxDynamicSharedMemorySize, dyn);
    topk_mask_kernel<<<rows, THREADS, dyn>>>(x, o, kp);
}

// round 4
// speedup vs baseline: 2.3521x; 1.3263x over previous
#include <cuda_runtime.h>
#include <cstdint>

// Row-wise top-k threshold mask.
// out[i,j] = x[i,j] if x[i,j] >= (k-th largest of row i) else 0.
// One CTA per row. 3-bit packed-counter first pass, candidate compaction,
// radix select on candidates. x re-read from gmem (L2-resident) — no smem staging.

constexpr int COLS    = 16384;
constexpr int THREADS = 512;
constexpr int VEC4    = COLS / THREADS / 4;   // 8 float4 per thread
constexpr int CAP     = 2048;                 // candidate buffer capacity

// Order-preserving float -> uint32 key (larger float => larger key)
__device__ __forceinline__ unsigned f2key(float f) {
    unsigned u = __float_as_uint(f);
    unsigned m = (unsigned)((int)u >> 31) | 0x80000000u;   // neg: ~u, pos: u|0x80000000
    return u ^ m;
}

// 256-bin (or fewer) block radix-select step. All THREADS call; tid<256 active in scan.
// Picks bucket containing the s_kk-th largest, updates *s_kk, returns digit.
__device__ __forceinline__ unsigned select_digit(
    int* s_hist, int* s_warp, int* s_kk, unsigned* s_digit, int tid, int lane)
{
    int h = 0, v = 0;
    if (tid < 256) {
        h = s_hist[255 - tid];
        v = h;
        #pragma unroll
        for (int o = 1; o < 32; o <<= 1) {
            int n = __shfl_up_sync(0xFFFFFFFFu, v, o);
            if (lane >= o) v += n;
        }
        if (lane == 31) s_warp[tid >> 5] = v;
    }
    __syncthreads();
    if (tid < 8) {
        int ws = s_warp[tid];
        #pragma unroll
        for (int o = 1; o < 8; o <<= 1) {
            int n = __shfl_up_sync(0xFFu, ws, o);
            if (tid >= o) ws += n;
        }
        s_warp[tid] = ws;
    }
    const int kk_cur = *s_kk;
    __syncthreads();
    if (tid < 256) {
        const int incl   = v + ((tid >= 32) ? s_warp[(tid >> 5) - 1] : 0); // count >= bucket
        const int cnt_gt = incl - h;                                       // count >  bucket
        if (cnt_gt < kk_cur && kk_cur <= incl) {
            *s_digit = (unsigned)(255 - tid);
            *s_kk    = kk_cur - cnt_gt;
        }
    }
    __syncthreads();
    return *s_digit;
}

__global__ __launch_bounds__(THREADS, 3)
void topk_mask_kernel(const float* __restrict__ x,
                      float* __restrict__ out,
                      const int* __restrict__ kptr)
{
    __shared__ int                s_hist[256];
    __shared__ int                s_warp[8];
    __shared__ unsigned long long s_wsum[16][2];   // per-warp packed 16-bit bin sums
    __shared__ int                s_hist8[8];
    __shared__ unsigned           s_cand[CAP];
    __shared__ int                s_ncand;
    __shared__ int                s_kk;
    __shared__ unsigned           s_digit;

    const int    tid  = threadIdx.x;
    const int    lane = tid & 31;
    const int    wid  = tid >> 5;
    const size_t base = (size_t)blockIdx.x * COLS;
    const float4* xv  = reinterpret_cast<const float4*>(x + base);

    if (tid == 0) { s_ncand = 0; s_kk = (kptr != nullptr) ? kptr[0] : 64; }

    // ---- Pass 1: 8-bin histogram on top 3 key bits, packed u64 counters ----
    unsigned long long acc0 = 0ull, acc1 = 0ull;
    #pragma unroll
    for (int j = 0; j < VEC4; j++) {
        float4 v = xv[tid + j * THREADS];
        const unsigned sx = (f2key(v.x) >> 26) & 0x38u;
        const unsigned sy = (f2key(v.y) >> 26) & 0x38u;
        const unsigned sz = (f2key(v.z) >> 26) & 0x38u;
        const unsigned sw = (f2key(v.w) >> 26) & 0x38u;
        acc0 += (1ull << sx) + (1ull << sz);
        acc1 += (1ull << sy) + (1ull << sw);
    }
    {
        const unsigned long long acc = acc0 + acc1;       // fields <= 32, no overflow
        const unsigned lo = (unsigned)acc, hi = (unsigned)(acc >> 32);
        // expand 8x8-bit -> 2x u64 of 4x16-bit fields (warp sums <= 1024 fit)
        unsigned long long w0 = (unsigned long long)__byte_perm(lo, 0, 0x4140)
                              | ((unsigned long long)__byte_perm(lo, 0, 0x4342) << 32);
        unsigned long long w1 = (unsigned long long)__byte_perm(hi, 0, 0x4140)
                              | ((unsigned long long)__byte_perm(hi, 0, 0x4342) << 32);
        #pragma unroll
        for (int o = 16; o > 0; o >>= 1) {
            w0 += __shfl_down_sync(0xFFFFFFFFu, w0, o);
            w1 += __shfl_down_sync(0xFFFFFFFFu, w1, o);
        }
        if (lane == 0) { s_wsum[wid][0] = w0; s_wsum[wid][1] = w1; }
    }
    __syncthreads();
    if (tid < 8) {
        const int word = tid >> 2, fld = (tid & 3) * 16;
        int total = 0;
        #pragma unroll
        for (int w = 0; w < 16; w++)
            total += (int)((s_wsum[w][word] >> fld) & 0xFFFFull);
        s_hist8[tid] = total;
    }
    __syncthreads();

    // select 3-bit bucket containing the k-th largest
    if (tid < 8) {
        int ge = 0;
        #pragma unroll
        for (int b = 0; b < 8; b++) if (b >= tid) ge += s_hist8[b];
        const int gt = ge - s_hist8[tid];
        const int kk = s_kk;
        if (gt < kk && kk <= ge) { s_digit = (unsigned)tid; s_kk = kk - gt; }
    }
    __syncthreads();

    unsigned prefix   = s_digit << 29;
    unsigned prefmask = 0xE0000000u;
    __syncthreads();

    // ---- Pass 2: compact candidates (top-3 bits match) from gmem (L2 hit) ----
    #pragma unroll
    for (int j = 0; j < VEC4; j++) {
        float4 v = xv[tid + j * THREADS];
        unsigned ks[4] = {f2key(v.x), f2key(v.y), f2key(v.z), f2key(v.w)};
        #pragma unroll
        for (int t = 0; t < 4; t++) {
            if ((ks[t] & prefmask) == prefix) {
                const int idx = atomicAdd(&s_ncand, 1);
                if (idx < CAP) s_cand[idx] = ks[t];
            }
        }
    }
    __syncthreads();
    const int  ncand  = s_ncand;
    const bool useBuf = (ncand <= CAP);

    // ---- Resolve remaining 29 bits: 4 radix passes (8,8,8,5 bits) ----
    const int      shifts[4] = {21, 13, 5, 0};
    const unsigned masks[4]  = {255u, 255u, 255u, 31u};
    #pragma unroll 1
    for (int p = 0; p < 4; p++) {
        const int      shift = shifts[p];
        const unsigned mask  = masks[p];

        if (tid < 256) s_hist[tid] = 0;
        __syncthreads();

        if (useBuf) {
            const int nloop = (ncand + THREADS - 1) / THREADS * THREADS;
            for (int i = tid; i < nloop; i += THREADS) {
                const unsigned key  = (i < ncand) ? s_cand[i] : 0u;
                const bool     cand = (i < ncand) && ((key & prefmask) == prefix);
                const unsigned d    = cand ? ((key >> shift) & mask) : 0xFFFFFFFFu;
                const unsigned m    = __match_any_sync(0xFFFFFFFFu, d);
                if (cand && lane == (__ffs(m) - 1)) atomicAdd(&s_hist[d], __popc(m));
            }
        } else {
            // slow path: full-row scan from gmem (degenerate rows only)
            #pragma unroll
            for (int j = 0; j < VEC4; j++) {
                float4 v = xv[tid + j * THREADS];
                unsigned ks[4] = {f2key(v.x), f2key(v.y), f2key(v.z), f2key(v.w)};
                #pragma unroll
                for (int t = 0; t < 4; t++) {
                    const bool     cand = ((ks[t] & prefmask) == prefix);
                    const unsigned d    = cand ? ((ks[t] >> shift) & mask) : 0xFFFFFFFFu;
                    const unsigned m    = __match_any_sync(0xFFFFFFFFu, d);
                    if (cand && lane == (__ffs(m) - 1)) atomicAdd(&s_hist[d], __popc(m));
                }
            }
        }
        __syncthreads();

        const unsigned dig = select_digit(s_hist, s_warp, &s_kk, &s_digit, tid, lane);
        prefix   |= dig << shift;
        prefmask |= mask << shift;
        __syncthreads();
    }

    const unsigned thresh = prefix;   // exact key of the k-th largest element

    // ---- Pass 3: masked write-back, re-read from gmem (L2 hit) ----
    float4* ov = reinterpret_cast<float4*>(out + base);
    #pragma unroll
    for (int j = 0; j < VEC4; j++) {
        float4 v = xv[tid + j * THREADS];
        float4 r;
        r.x = (f2key(v.x) >= thresh) ? v.x : 0.0f;
        r.y = (f2key(v.y) >= thresh) ? v.y : 0.0f;
        r.z = (f2key(v.z) >= thresh) ? v.z : 0.0f;
        r.w = (f2key(v.w) >= thresh) ? v.w : 0.0f;
        ov[tid + j * THREADS] = r;
    }
}

extern "C" void kernel_launch(void* const* d_in, const int* in_sizes, int n_in,
                              void* d_out, int out_size)
{
    const float* x  = (const float*)d_in[0];
    const int*   kp = (n_in >= 2) ? (const int*)d_in[1] : nullptr;
    float*       o  = (float*)d_out;

    const int rows = in_sizes[0] / COLS;
    topk_mask_kernel<<<rows, THREADS>>>(x, o, kp);
}